// round 12
// baseline (speedup 1.0000x reference)
#include <cuda_runtime.h>
#include <cuda_fp16.h>
#include <math.h>
#include <stdint.h>

// ===========================================================================
// ExtractorLoss, fp16 mma.sync GEMM + half-period DFT fold + fused reduction:
//   K1 prep : zero acc/counter; fold x -> fp16 x_e/x_o (8-elem items, uint4
//             stores); basis -> fp16 (8-elem items). ~1 item/thread.
//   K2 gemm : A16*W16 (fp32), psd in-register, per-row (tot,wan) fixed-point
//             u64 atomics; LAST CTA reduces g_acc -> -mean(snr) -> out[0].
// ===========================================================================

#define BMAX   4096
#define TMAXE  3648
#define BM     128
#define BN     112
#define KC     64           // K elems per chunk: 128B rows in smem
#define FIXS   1048576.0f   // 2^20 fixed-point scale (associative -> deterministic)

__device__ __align__(16) __half g_xe[BMAX * TMAXE];       // even-class fold
__device__ __align__(16) __half g_xo[BMAX * TMAXE];       // odd-class fold
__device__ __align__(16) __half g_w16[2 * 224 * TMAXE];   // [class][col][t]
__device__ unsigned long long g_acc[BMAX * 2];            // [row]{tot,wan} fixed-pt
__device__ unsigned int g_done;                           // CTA completion counter

// smem per buffer: A(128 rows x 128B = 16K) + B(112 rows = 14K) = 30K; x2
#define SM_A 0u
#define SM_B 16384u
#define BUF_BYTES 30720u
#define SMEM_TOTAL (2u * BUF_BYTES)

// ---------------- PTX helpers ----------------------------------------------
__device__ __forceinline__ uint32_t smem_u32(const void* p) {
    uint32_t a;
    asm("{ .reg .u64 t; cvta.to.shared.u64 t, %1; cvt.u32.u64 %0, t; }"
        : "=r"(a) : "l"(p));
    return a;
}
__device__ __forceinline__ void cp_async16(uint32_t dst, const void* src, int sz) {
    asm volatile("cp.async.cg.shared.global [%0], [%1], 16, %2;"
                 :: "r"(dst), "l"(src), "r"(sz) : "memory");
}
#define CP_COMMIT() asm volatile("cp.async.commit_group;" ::: "memory")
#define CP_WAIT(n)  asm volatile("cp.async.wait_group %0;" :: "n"(n) : "memory")

__device__ __forceinline__ void ldsm4(uint32_t* r, uint32_t a) {
    asm volatile("ldmatrix.sync.aligned.m8n8.x4.shared.b16 {%0,%1,%2,%3}, [%4];"
                 : "=r"(r[0]), "=r"(r[1]), "=r"(r[2]), "=r"(r[3]) : "r"(a));
}
__device__ __forceinline__ void ldsm2(uint32_t* r, uint32_t a) {
    asm volatile("ldmatrix.sync.aligned.m8n8.x2.shared.b16 {%0,%1}, [%2];"
                 : "=r"(r[0]), "=r"(r[1]) : "r"(a));
}
__device__ __forceinline__ void mma_f16(float* c, const uint32_t* a,
                                        const uint32_t* b) {
    asm volatile(
        "mma.sync.aligned.m16n8k16.row.col.f32.f16.f16.f32 "
        "{%0,%1,%2,%3}, {%4,%5,%6,%7}, {%8,%9}, {%0,%1,%2,%3};"
        : "+f"(c[0]), "+f"(c[1]), "+f"(c[2]), "+f"(c[3])
        : "r"(a[0]), "r"(a[1]), "r"(a[2]), "r"(a[3]), "r"(b[0]), "r"(b[1]));
}

// swizzled byte offset of (row r, 16B-chunk kc) in a 128B-row tile
__device__ __forceinline__ uint32_t swz(int r, int kc) {
    return (uint32_t)r * 128u + (uint32_t)((kc ^ (r & 7)) << 4);
}

// fold length + mode. half=1: parity classes over 30*fs. half=0: single class.
__device__ __forceinline__ int fold_info(int fs, int T, int* half) {
    int P2 = 30 * fs;
    if (P2 > 0 && P2 <= T && (T % P2) == 0) { *half = 1; return P2; }
    int P = 60 * fs;
    if (P > 0 && P <= T && (T % P) == 0) { *half = 0; return P; }
    *half = 0;
    return T;
}

// class/local-bin mapping helpers (must agree between prep and gemm epilogue)
__device__ __forceinline__ int bin_class(int g, int fmin, int samp, int half) {
    return half ? ((fmin + g * samp) & 1) : 0;
}
__device__ __forceinline__ int bin_local(int g, int samp, int half) {
    return (half && (samp & 1)) ? (g >> 1) : g;
}
// inverse: local j of class P -> global g; returns count nP via *np
__device__ __forceinline__ void class_geom(int P, int fmin, int samp, int ngrid,
                                           int half, int* gstart, int* gstep,
                                           int* np) {
    if (half) {
        if (samp & 1) {
            int gs = (P == (fmin & 1)) ? 0 : 1;
            *gstart = gs; *gstep = 2;
            *np = (gs < ngrid) ? ((ngrid - gs + 1) >> 1) : 0;
        } else {
            if (P == (fmin & 1)) { *gstart = 0; *gstep = 1; *np = ngrid; }
            else                 { *gstart = 0; *gstep = 1; *np = 0; }
        }
    } else {
        if (P == 0) { *gstart = 0; *gstep = 1; *np = ngrid; }
        else        { *gstart = 0; *gstep = 1; *np = 0; }
    }
}

// JAX-faithful basis value: fp32 phase, exact DP range reduction, fp32 trig
__device__ __forceinline__ float basis_val(int fs, int fmin, int samp,
                                           int g, int odd, int t) {
    float fHz = (float)(fmin + g * samp) / 60.0f;
    float s   = (float)(6.283185307179586 / (double)fs);
    float ph  = (s * fHz) * (float)t;            // JAX fp32 rounding order
    double dph = (double)ph;
    double r = dph - floor(dph * 0.15915494309189535) * 6.283185307179586;
    if (r > 3.141592653589793) r -= 6.283185307179586;
    float rf = (float)r;
    return odd ? sinf(rf) : cosf(rf);
}

__device__ __forceinline__ uint32_t pack2h(float a, float b) {
    __half2 h = __floats2half2_rn(a, b);
    return *(uint32_t*)&h;
}

// ---------------------------------------------------------------------------
// K1: prep, grid-stride over [zero acc | fold 8-elem items | basis 8-elem].
// Tail items write explicit zeros into the [Tfold, Kp) pad.
// ---------------------------------------------------------------------------
__global__ void prep_kernel(const float* __restrict__ x,
                            const int* __restrict__ fs_p,
                            const int* __restrict__ samp_p,
                            const int* __restrict__ fmin_p,
                            const int* __restrict__ fmax_p,
                            int T, int B) {
    const int fs = *fs_p, samp = *samp_p, fmin = *fmin_p, fmax = *fmax_p;
    int half;
    const int Tfold = fold_info(fs, T, &half);
    const int Kp = (Tfold + 7) & ~7;           // storage row stride (halfs)
    const int nper = T / Tfold;
    const int ngrid = (fmax - fmin) / samp + 1;
    const bool vec4 = ((Tfold & 3) == 0) && ((T & 3) == 0);

    const int tq8 = Kp >> 3;                   // 8-elem items per row
    const long long nzero  = 2ll * BMAX;
    const long long nfold  = (long long)B * tq8;
    const long long nbasis = 2ll * ngrid * tq8;
    const long long total  = nzero + nfold + nbasis;
    const long long stride = (long long)gridDim.x * blockDim.x;

    for (long long w = (long long)blockIdx.x * blockDim.x + threadIdx.x;
         w < total; w += stride) {
        if (w < nzero) {
            g_acc[w] = 0ull;
            if (w == 0) g_done = 0u;
            continue;
        }
        long long w1 = w - nzero;
        if (w1 < nfold) {
            const int b  = (int)(w1 / tq8);
            const int t0 = ((int)(w1 - (long long)b * tq8)) << 3;
            float se[8], so[8];
#pragma unroll
            for (int e = 0; e < 8; e++) { se[e] = 0.f; so[e] = 0.f; }
            if (vec4 && t0 + 8 <= Tfold) {
                const float* base = x + (size_t)b * T + t0;
                for (int j = 0; j < nper; j++) {
                    float4 v0 = *(const float4*)(base + (size_t)j * Tfold);
                    float4 v1 = *(const float4*)(base + (size_t)j * Tfold + 4);
                    float sg = (j & 1) ? -1.f : 1.f;
                    se[0] += v0.x; so[0] += sg * v0.x;
                    se[1] += v0.y; so[1] += sg * v0.y;
                    se[2] += v0.z; so[2] += sg * v0.z;
                    se[3] += v0.w; so[3] += sg * v0.w;
                    se[4] += v1.x; so[4] += sg * v1.x;
                    se[5] += v1.y; so[5] += sg * v1.y;
                    se[6] += v1.z; so[6] += sg * v1.z;
                    se[7] += v1.w; so[7] += sg * v1.w;
                }
            } else {
                for (int e = 0; e < 8; e++) {
                    int t = t0 + e;
                    if (t >= Tfold) break;        // pad elems stay 0
                    for (int j = 0; j < nper; j++) {
                        float v = x[(size_t)b * T + t + (size_t)j * Tfold];
                        se[e] += v;
                        so[e] += (j & 1) ? -v : v;
                    }
                }
            }
            uint4 pe, po;
            pe.x = pack2h(se[0], se[1]); pe.y = pack2h(se[2], se[3]);
            pe.z = pack2h(se[4], se[5]); pe.w = pack2h(se[6], se[7]);
            *(uint4*)(g_xe + (size_t)b * Kp + t0) = pe;
            if (half) {
                po.x = pack2h(so[0], so[1]); po.y = pack2h(so[2], so[3]);
                po.z = pack2h(so[4], so[5]); po.w = pack2h(so[6], so[7]);
                *(uint4*)(g_xo + (size_t)b * Kp + t0) = po;
            }
            continue;
        }
        long long w2 = w1 - nfold;
        const int c  = (int)(w2 / tq8);
        const int t0 = ((int)(w2 - (long long)c * tq8)) << 3;
        const int g = c >> 1, odd = c & 1;
        float v[8];
#pragma unroll
        for (int e = 0; e < 8; e++) {
            int t = t0 + e;
            v[e] = (t < Tfold) ? basis_val(fs, fmin, samp, g, odd, t) : 0.f;
        }
        const int P = bin_class(g, fmin, samp, half);
        const int j = bin_local(g, samp, half);
        const int col = 2 * j + odd;
        uint4 pw;
        pw.x = pack2h(v[0], v[1]); pw.y = pack2h(v[2], v[3]);
        pw.z = pack2h(v[4], v[5]); pw.w = pack2h(v[6], v[7]);
        *(uint4*)(g_w16 + ((size_t)P * 224 + col) * Kp + t0) = pw;
    }
}

// ---------------------------------------------------------------------------
// K2: GEMM via mma.sync. grid (B/128, 2 Ntiles, 2 classes); 512 thr =
// 16 warps (8m x 2n). Epilogue: psd -> per-row (tot,wan) -> u64 atomics.
// Last CTA (g_done counter) reduces g_acc -> -mean(snr) -> out[0].
// ---------------------------------------------------------------------------
extern __shared__ __align__(128) uint8_t dynsm[];

__global__ __launch_bounds__(512, 1) void gemm_mma(float* __restrict__ out,
                                                   const int* __restrict__ ftrue,
                                                   const int* __restrict__ fs_p,
                                                   const int* __restrict__ samp_p,
                                                   const int* __restrict__ delta_p,
                                                   const int* __restrict__ fmin_p,
                                                   const int* __restrict__ fmax_p,
                                                   int Brows, int T, int nCTA) {
    const int fs = *fs_p, samp = *samp_p, fmin = *fmin_p, fmax = *fmax_p;
    const int delta = *delta_p;
    int half;
    const int Tfold = fold_info(fs, T, &half);
    const int Kp = (Tfold + 7) & ~7;
    const int chunks = (Kp + KC - 1) / KC;
    const int ngrid = (fmax - fmin) / samp + 1;

    const int P = blockIdx.z;
    int gstart, gstep, nP;
    class_geom(P, fmin, samp, ngrid, half, &gstart, &gstep, &nP);

    const int tid  = threadIdx.x;
    const int lane = tid & 31;
    const int warp = tid >> 5;

    if (nP > 0) {
        const int wm   = warp & 7;        // 0..7 -> 16-row slice
        const int wn   = warp >> 3;       // 0..1 -> 56-col slice
        const int rowBase = blockIdx.x * BM;
        const int colBase = blockIdx.y * BN;

        const uint32_t smb = smem_u32(dynsm);

        const __half* A = (P == 0 ? g_xe : g_xo) + (size_t)rowBase * Kp;
        const __half* Bw = g_w16 + ((size_t)P * 224 + colBase) * Kp;

        float acc[7][4];
#pragma unroll
        for (int j = 0; j < 7; j++)
#pragma unroll
            for (int q = 0; q < 4; q++) acc[j][q] = 0.f;

        auto fill = [&](int buf, int chunk) {
            const int k0 = chunk * KC;
            const uint32_t bb = smb + (uint32_t)buf * BUF_BYTES;
            for (int idx = tid; idx < 1920; idx += 512) {
                const __half* src;
                uint32_t sec;
                int r;
                if (idx < 1024) { sec = SM_A; src = A;  r = idx >> 3; }
                else            { sec = SM_B; src = Bw; r = (idx - 1024) >> 3; }
                const int c = idx & 7;
                const int k = k0 + c * 8;
                cp_async16(bb + sec + swz(r, c), src + (size_t)r * Kp + k,
                           (k < Kp) ? 16 : 0);
            }
        };

        auto compute = [&](int buf) {
            const uint32_t bb = smb + (uint32_t)buf * BUF_BYTES;
#pragma unroll
            for (int ks = 0; ks < 4; ks++) {
                uint32_t a4[4], bfr[7][2];
                {
                    const int rA  = wm * 16 + (lane & 15);
                    const int kcA = ks * 2 + (lane >> 4);
                    ldsm4(a4, bb + SM_A + swz(rA, kcA));
                }
                {
                    const int rb  = ((lane >> 4) & 1) * 8 + (lane & 7);
                    const int kcB = ks * 2 + ((lane >> 3) & 1);
#pragma unroll
                    for (int jp = 0; jp < 3; jp++) {
                        const int r = wn * 56 + jp * 16 + rb;
                        uint32_t t4[4];
                        ldsm4(t4, bb + SM_B + swz(r, kcB));
                        bfr[2 * jp][0] = t4[0]; bfr[2 * jp][1] = t4[1];
                        bfr[2 * jp + 1][0] = t4[2]; bfr[2 * jp + 1][1] = t4[3];
                    }
                    {
                        const int r = wn * 56 + 48 + (lane & 7);
                        const int kc2 = ks * 2 + ((lane >> 3) & 1);
                        ldsm2(bfr[6], bb + SM_B + swz(r, kc2));
                    }
                }
#pragma unroll
                for (int j = 0; j < 7; j++) mma_f16(acc[j], a4, bfr[j]);
            }
        };

        fill(0, 0);
        CP_COMMIT();
        int buf = 0;
        for (int c = 0; c < chunks; ++c) {
            if (c + 1 < chunks) { fill(buf ^ 1, c + 1); CP_COMMIT(); }
            if (c + 1 < chunks) CP_WAIT(1); else CP_WAIT(0);
            __syncthreads();
            compute(buf);
            __syncthreads();
            buf ^= 1;
        }

        // fused epilogue: psd -> per-row masked partial sums -> atomics
        {
            const int row0 = rowBase + wm * 16 + (lane >> 2);   // and row0+8
            const int f0 = ftrue[row0];
            const int f1 = ftrue[row0 + 8];
            float t0 = 0.f, w0 = 0.f, t1 = 0.f, w1 = 0.f;
#pragma unroll
            for (int j = 0; j < 7; j++) {
                const int jl = (colBase >> 1) + wn * 28 + j * 4 + (lane & 3);
                if (jl < nP) {
                    const int g  = gstart + jl * gstep;
                    const int fb = fmin + g * samp;
                    const float* cc = acc[j];
                    const float p0 = cc[0] * cc[0] + cc[1] * cc[1];
                    const float p1 = cc[2] * cc[2] + cc[3] * cc[3];
                    t0 += p0; t1 += p1;
                    int d0 = fb - f0; if (d0 < 0) d0 = -d0;
                    int d1 = fb - f1; if (d1 < 0) d1 = -d1;
                    if (d0 <= delta) w0 += p0;
                    if (d1 <= delta) w1 += p1;
                }
            }
#pragma unroll
            for (int o = 1; o <= 2; o <<= 1) {
                t0 += __shfl_xor_sync(0xFFFFFFFFu, t0, o);
                w0 += __shfl_xor_sync(0xFFFFFFFFu, w0, o);
                t1 += __shfl_xor_sync(0xFFFFFFFFu, t1, o);
                w1 += __shfl_xor_sync(0xFFFFFFFFu, w1, o);
            }
            if ((lane & 3) == 0) {
                atomicAdd(&g_acc[2 * row0],           (unsigned long long)llrintf(t0 * FIXS));
                atomicAdd(&g_acc[2 * row0 + 1],       (unsigned long long)llrintf(w0 * FIXS));
                atomicAdd(&g_acc[2 * (row0 + 8)],     (unsigned long long)llrintf(t1 * FIXS));
                atomicAdd(&g_acc[2 * (row0 + 8) + 1], (unsigned long long)llrintf(w1 * FIXS));
            }
        }
    }

    // ---- last-CTA finalize: snr per row + deterministic mean -> out[0] ----
    __shared__ unsigned int s_last;
    __shared__ float red[16];
    __syncthreads();
    if (tid == 0) {
        __threadfence();
        s_last = (atomicAdd(&g_done, 1u) + 1u == (unsigned)nCTA) ? 1u : 0u;
    }
    __syncthreads();
    if (s_last) {
        const int nw = 2 * delta / samp + 1;
        const int nu = ngrid - nw;
        float s = 0.f;
        for (int i = tid; i < Brows; i += 512) {
            float tot = (float)((long long)g_acc[2 * i])     * (1.0f / FIXS);
            float wan = (float)((long long)g_acc[2 * i + 1]) * (1.0f / FIXS);
            float t1 = wan / (float)nw;
            float t2 = (tot - wan) / (float)nu;
            s += 10.0f * log10f(t1 / t2);
        }
#pragma unroll
        for (int o = 16; o > 0; o >>= 1) s += __shfl_xor_sync(0xFFFFFFFFu, s, o);
        if (lane == 0) red[warp] = s;
        __syncthreads();
        if (warp == 0) {
            s = (lane < 16) ? red[lane] : 0.f;
#pragma unroll
            for (int o = 8; o > 0; o >>= 1) s += __shfl_xor_sync(0xFFFFFFFFu, s, o);
            if (lane == 0) out[0] = -(s / (float)Brows);
        }
    }
}

// ---------------------------------------------------------------------------
extern "C" void kernel_launch(void* const* d_in, const int* in_sizes, int n_in,
                              void* d_out, int out_size) {
    const float* x     = (const float*)d_in[0];
    const int*   ftrue = (const int*)  d_in[1];
    const int*   fs    = (const int*)  d_in[2];
    const int*   delta = (const int*)  d_in[3];
    const int*   samp  = (const int*)  d_in[4];
    const int*   fmin  = (const int*)  d_in[5];
    const int*   fmax  = (const int*)  d_in[6];

    const int B = in_sizes[1];
    const int T = in_sizes[0] / B;

    prep_kernel<<<2048, 256>>>(x, fs, samp, fmin, fmax, T, B);

    cudaFuncSetAttribute(gemm_mma, cudaFuncAttributeMaxDynamicSharedMemorySize,
                         SMEM_TOTAL);
    const dim3 grid(B / BM, 2, 2);
    const int nCTA = grid.x * grid.y * grid.z;
    gemm_mma<<<grid, 512, SMEM_TOTAL>>>((float*)d_out, ftrue, fs, samp, delta,
                                        fmin, fmax, B, T, nCTA);
}